// round 1
// baseline (speedup 1.0000x reference)
#include <cuda_runtime.h>
#include <math.h>

// ---------------- problem constants ----------------
#define B_   64
#define C_   256
#define HW_  4096          // 64*64
#define TILE 32            // spatial positions per block in pass1
#define NTILES (HW_ / TILE)  // 128
#define PLANES 128
#define HIDDEN 16
#define K_   8
#define ATT_CH 4
#define EPS_ 1e-5f

// ---------------- device scratch (no allocations allowed) ----------------
__device__ float g_sumc[B_ * C_];   // per (b,c): sum over all s of x  -> beta_c
__device__ float g_num [B_ * C_];   // per (b,c): sum over s of x*exp(logit_s)
__device__ float g_D   [B_];        // per b: sum over s of exp(logit_s)
__device__ float g_suma[B_];        // per b: sum over s of (sum over c of x)
__device__ float g_summ[B_];        // per b: sum over s of (max over c of x)

// ---------------- kernel 0: zero the accumulators ----------------
__global__ void zero_accum() {
    int i = blockIdx.x * blockDim.x + threadIdx.x;   // 64*256 = 16384 threads
    if (i < B_ * C_) { g_sumc[i] = 0.f; g_num[i] = 0.f; }
    if (i < B_)      { g_D[i] = 0.f; g_suma[i] = 0.f; g_summ[i] = 0.f; }
}

// ---------------- kernel 1: single streaming pass over x ----------------
__global__ __launch_bounds__(256) void pass1(const float* __restrict__ x,
                                             const float* __restrict__ w_mask,
                                             const float* __restrict__ b_mask) {
    __shared__ float sx[C_][TILE];       // 32 KB: x tile, row stride 32 -> bank = j
    __shared__ float sw[C_];             // mask weights
    __shared__ float aux_l[8][TILE];     // per-part partial logits
    __shared__ float aux_s[8][TILE];     // per-part partial channel sums
    __shared__ float aux_m[8][TILE];     // per-part partial channel maxes
    __shared__ float se[TILE];           // exp(logit_j)

    const int t    = threadIdx.x;        // 0..255
    const int w    = t >> 5;             // warp / "part" 0..7
    const int lane = t & 31;
    const int b    = blockIdx.y;         // batch
    const int tile = blockIdx.x;         // spatial tile

    sw[t] = w_mask[t];

    // ---- coalesced tile load: each warp loads 4 rows/iter (lanes 0-7 one row) ----
    const float4* xb = reinterpret_cast<const float4*>(x)
                     + (size_t)b * C_ * (HW_ / 4) + (size_t)tile * (TILE / 4);
    #pragma unroll
    for (int it = 0; it < 8; ++it) {
        int c = it * 32 + w * 4 + (lane >> 3);
        int i = lane & 7;
        float4 v = xb[(size_t)c * (HW_ / 4) + i];
        *reinterpret_cast<float4*>(&sx[c][i * 4]) = v;
    }
    __syncthreads();

    // ---- per-position reductions over channels (part = warp, j = lane) ----
    {
        float lp = 0.f, sp = 0.f, mp = -1e30f;
        #pragma unroll 8
        for (int cc = 0; cc < 32; ++cc) {
            int c = w * 32 + cc;
            float v = sx[c][lane];
            lp = fmaf(v, sw[c], lp);
            sp += v;
            mp = fmaxf(mp, v);
        }
        aux_l[w][lane] = lp; aux_s[w][lane] = sp; aux_m[w][lane] = mp;
    }
    __syncthreads();

    if (t < TILE) {
        float l = b_mask[0], s = 0.f, m = -1e30f;
        #pragma unroll
        for (int p = 0; p < 8; ++p) {
            l += aux_l[p][t];
            s += aux_s[p][t];
            m  = fmaxf(m, aux_m[p][t]);
        }
        float ej = __expf(l);      // unnormalized softmax weight (logits are O(3))
        se[t] = ej;
        // warp-reduce the three block scalars
        #pragma unroll
        for (int off = 16; off > 0; off >>= 1) {
            ej += __shfl_down_sync(0xffffffffu, ej, off);
            s  += __shfl_down_sync(0xffffffffu, s,  off);
            m  += __shfl_down_sync(0xffffffffu, m,  off);
        }
        if (t == 0) {
            atomicAdd(&g_D[b],    ej);
            atomicAdd(&g_suma[b], s);
            atomicAdd(&g_summ[b], m);
        }
    }
    __syncthreads();

    // ---- per-channel accumulation (thread t owns channel t); rotated index
    //      jj=(q+c)&31 keeps both sx and se reads bank-conflict-free ----
    {
        const int c = t;
        float sv = 0.f, sve = 0.f;
        #pragma unroll 8
        for (int q = 0; q < TILE; ++q) {
            int jj = (q + c) & (TILE - 1);
            float v = sx[c][jj];
            sv += v;
            sve = fmaf(v, se[jj], sve);
        }
        atomicAdd(&g_sumc[b * C_ + c], sv);
        atomicAdd(&g_num [b * C_ + c], sve);
    }
}

// ---------------- kernel 2: per-batch finalizer (all the tiny math) ----------------
__global__ __launch_bounds__(256) void finalize(
        const float* __restrict__ w_cm1, const float* __restrict__ b_cm1,
        const float* __restrict__ ln_w,  const float* __restrict__ ln_b,
        const float* __restrict__ w_cm2, const float* __restrict__ b_cm2,
        const float* __restrict__ w_net1, const float* __restrict__ w_net2,
        const float* __restrict__ w_fc,
        const float* __restrict__ bn_w,  const float* __restrict__ bn_b,
        const float* __restrict__ bn_mean, const float* __restrict__ bn_var,
        const float* __restrict__ w_kfc,
        float* __restrict__ out) {
    __shared__ float ctx[C_], bc[C_], tg[PLANES], sout[C_];
    __shared__ float red_s[4], red_q[4];
    __shared__ float hid[HIDDEN], o8[K_], kar[ATT_CH], fv[K_];

    const int t = threadIdx.x;       // 0..255
    const int b = blockIdx.x;        // batch
    const int lane = t & 31, wp = t >> 5;

    const float invD = 1.f / g_D[b];
    const float aval = g_suma[b] * (1.f / ((float)C_ * (float)HW_));
    const float mval = g_summ[b] * (1.f / (float)HW_);

    ctx[t] = g_num [b * C_ + t] * invD;
    bc[t]  = g_sumc[b * C_ + t] * (1.f / (float)HW_);
    __syncthreads();

    // context_modeling conv1: t < 128 planes, dot over 256 channels
    float tv = 0.f;
    if (t < PLANES) {
        float acc = b_cm1[t];
        const float* wr = w_cm1 + t * C_;
        #pragma unroll 8
        for (int c = 0; c < C_; ++c) acc = fmaf(ctx[c], wr[c], acc);
        tv = acc;
    }
    // LayerNorm over 128 values (threads >=128 contribute zeros)
    float s1 = tv, s2 = tv * tv;
    #pragma unroll
    for (int off = 16; off > 0; off >>= 1) {
        s1 += __shfl_down_sync(0xffffffffu, s1, off);
        s2 += __shfl_down_sync(0xffffffffu, s2, off);
    }
    if (t < PLANES && lane == 0) { red_s[wp] = s1; red_q[wp] = s2; }
    __syncthreads();
    if (t < PLANES) {
        float S  = red_s[0] + red_s[1] + red_s[2] + red_s[3];
        float SQ = red_q[0] + red_q[1] + red_q[2] + red_q[3];
        float mu  = S * (1.f / PLANES);
        float var = SQ * (1.f / PLANES) - mu * mu;
        float tn = (tv - mu) * rsqrtf(var + EPS_) * ln_w[t] + ln_b[t];
        tg[t] = 0.5f * tn * (1.f + erff(tn * 0.70710678118654752f));   // exact GELU
    }
    __syncthreads();

    // context_modeling conv2 + assemble out = beta_c + beta_g + beta_s
    {
        float acc = b_cm2[t];
        const float* wr = w_cm2 + t * PLANES;
        #pragma unroll 8
        for (int p = 0; p < PLANES; ++p) acc = fmaf(tg[p], wr[p], acc);
        sout[t] = bc[t] + acc + ((t & 1) ? mval : aval);
    }
    __syncthreads();

    if (t < HIDDEN) {
        float h = 0.f;
        const float* wr = w_net1 + t * C_;
        #pragma unroll 8
        for (int c = 0; c < C_; ++c) h = fmaf(sout[c], wr[c], h);
        hid[t] = fmaxf(h, 0.f);
    }
    __syncthreads();
    if (t < K_) {
        float o = 0.f;
        #pragma unroll
        for (int q = 0; q < HIDDEN; ++q) o = fmaf(hid[q], w_net2[t * HIDDEN + q], o);
        o8[t] = o;
    }
    __syncthreads();
    if (t < ATT_CH) {
        float ka = 0.f;
        #pragma unroll
        for (int k = 0; k < K_; ++k) ka = fmaf(o8[k], w_fc[t * K_ + k], ka);
        ka = (ka - bn_mean[t]) * rsqrtf(bn_var[t] + EPS_) * bn_w[t] + bn_b[t];
        kar[t] = fmaxf(ka, 0.f);
    }
    __syncthreads();
    if (t < K_) {
        float kk = 0.f;
        #pragma unroll
        for (int q = 0; q < ATT_CH; ++q) kk = fmaf(kar[q], w_kfc[t * ATT_CH + q], kk);
        float ker = 1.f / (1.f + __expf(-kk));
        fv[t] = o8[t] * ker * (1.f / 30.f);
    }
    __syncthreads();
    if (t == 0) {
        float mx = -1e30f;
        #pragma unroll
        for (int k = 0; k < K_; ++k) mx = fmaxf(mx, fv[k]);
        float e[K_], s = 0.f;
        #pragma unroll
        for (int k = 0; k < K_; ++k) { e[k] = __expf(fv[k] - mx); s += e[k]; }
        float inv = 1.f / s;
        #pragma unroll
        for (int k = 0; k < K_; ++k) out[b * K_ + k] = e[k] * inv;
    }
}

// ---------------- launch ----------------
extern "C" void kernel_launch(void* const* d_in, const int* in_sizes, int n_in,
                              void* d_out, int out_size) {
    const float* x      = (const float*)d_in[0];
    const float* w_mask = (const float*)d_in[1];
    const float* b_mask = (const float*)d_in[2];
    const float* w_cm1  = (const float*)d_in[3];
    const float* b_cm1  = (const float*)d_in[4];
    const float* ln_w   = (const float*)d_in[5];
    const float* ln_b   = (const float*)d_in[6];
    const float* w_cm2  = (const float*)d_in[7];
    const float* b_cm2  = (const float*)d_in[8];
    const float* w_net1 = (const float*)d_in[9];
    const float* w_net2 = (const float*)d_in[10];
    const float* w_fc   = (const float*)d_in[11];
    const float* bn_w   = (const float*)d_in[12];
    const float* bn_b   = (const float*)d_in[13];
    const float* bn_mean= (const float*)d_in[14];
    const float* bn_var = (const float*)d_in[15];
    const float* w_kfc  = (const float*)d_in[16];
    float* out = (float*)d_out;

    zero_accum<<<64, 256>>>();
    pass1<<<dim3(NTILES, B_), 256>>>(x, w_mask, b_mask);
    finalize<<<B_, 256>>>(w_cm1, b_cm1, ln_w, ln_b, w_cm2, b_cm2,
                          w_net1, w_net2, w_fc, bn_w, bn_b, bn_mean, bn_var,
                          w_kfc, out);
}